// round 1
// baseline (speedup 1.0000x reference)
#include <cuda_runtime.h>
#include <cuda_bf16.h>

#define NEG_CONST 10000.0f

// Scratch (device globals: no allocation allowed in kernel_launch).
// B*S = 4096 for this problem; sized with headroom.
__device__ float g_score[65536];
__device__ int   g_idx[65536];

// ---------------------------------------------------------------------------
// Kernel 0: zero the score accumulator
// ---------------------------------------------------------------------------
__global__ void tp_zero_kernel(int n) {
    int i = blockIdx.x * blockDim.x + threadIdx.x;
    if (i < n) g_score[i] = 0.0f;
}

// ---------------------------------------------------------------------------
// Kernel 1: column sum of attention_probs over (h, q), weighted by head_masks.
// A layout: [B,H,S,S], key dim contiguous. Each thread owns one float4 of key
// columns and loops over a q-slice; fully coalesced 128B transactions.
// grid = (ceil(S/4/256), Q_SPLITS, B*H), block = 256
// ---------------------------------------------------------------------------
__global__ void tp_colsum_kernel(const float4* __restrict__ A,
                                 const float* __restrict__ hm,
                                 int S, int H, int q_per_block) {
    int bh = blockIdx.z;
    int b  = bh / H;
    int h  = bh % H;
    int S4 = S >> 2;
    int k4 = blockIdx.x * blockDim.x + threadIdx.x;
    if (k4 >= S4) return;

    int q0   = blockIdx.y * q_per_block;
    int qend = min(q_per_block, S - q0);

    const float4* p = A + ((long)bh * S + q0) * (long)S4 + k4;

    float4 a0 = make_float4(0.f, 0.f, 0.f, 0.f);
    float4 a1 = make_float4(0.f, 0.f, 0.f, 0.f);
    float4 a2 = make_float4(0.f, 0.f, 0.f, 0.f);
    float4 a3 = make_float4(0.f, 0.f, 0.f, 0.f);

    int q = 0;
    for (; q + 4 <= qend; q += 4) {
        float4 v0 = p[(long)(q + 0) * S4];
        float4 v1 = p[(long)(q + 1) * S4];
        float4 v2 = p[(long)(q + 2) * S4];
        float4 v3 = p[(long)(q + 3) * S4];
        a0.x += v0.x; a0.y += v0.y; a0.z += v0.z; a0.w += v0.w;
        a1.x += v1.x; a1.y += v1.y; a1.z += v1.z; a1.w += v1.w;
        a2.x += v2.x; a2.y += v2.y; a2.z += v2.z; a2.w += v2.w;
        a3.x += v3.x; a3.y += v3.y; a3.z += v3.z; a3.w += v3.w;
    }
    for (; q < qend; ++q) {
        float4 v = p[(long)q * S4];
        a0.x += v.x; a0.y += v.y; a0.z += v.z; a0.w += v.w;
    }
    float4 acc;
    acc.x = (a0.x + a1.x) + (a2.x + a3.x);
    acc.y = (a0.y + a1.y) + (a2.y + a3.y);
    acc.z = (a0.z + a1.z) + (a2.z + a3.z);
    acc.w = (a0.w + a1.w) + (a2.w + a3.w);

    float w = hm[h];
    float* sp = g_score + (long)b * S + 4 * (long)k4;
    atomicAdd(sp + 0, acc.x * w);
    atomicAdd(sp + 1, acc.y * w);
    atomicAdd(sp + 2, acc.z * w);
    atomicAdd(sp + 3, acc.w * w);
}

// ---------------------------------------------------------------------------
// Kernel 2: per batch: threshold, stable compaction (block scan), write
// padded_idx and the rewritten attention mask.
// grid = B, block = 1024 (handles S <= 2048, 2 elems/thread)
// ---------------------------------------------------------------------------
__global__ void tp_prune_scan_kernel(const float* __restrict__ hm, int H,
                                     const float* __restrict__ attn_mask,
                                     const float* __restrict__ thr,
                                     float* __restrict__ am_out, int S) {
    int b = blockIdx.x;
    int t = threadIdx.x;

    __shared__ float sh_inv;
    __shared__ int tmp[1024];

    if (t == 0) {
        float s = 0.f;
        for (int h = 0; h < H; ++h) s += hm[h];
        sh_inv = 1.0f / s;
    }
    __syncthreads();

    float inv = sh_inv;
    float th  = thr[0];

    int e0 = 2 * t, e1 = 2 * t + 1;
    int k0 = 0, k1 = 0;
    if (e0 < S) {
        float s = g_score[(long)b * S + e0] * inv + (e0 == 0 ? 100.0f : 0.0f);
        k0 = (s > th) ? 1 : 0;
    }
    if (e1 < S) {
        float s = g_score[(long)b * S + e1] * inv;
        k1 = (s > th) ? 1 : 0;
    }
    int pair = k0 + k1;

    tmp[t] = pair;
    __syncthreads();
    // Hillis-Steele inclusive scan over 1024 partials
    for (int off = 1; off < 1024; off <<= 1) {
        int v = (t >= off) ? tmp[t - off] : 0;
        __syncthreads();
        tmp[t] += v;
        __syncthreads();
    }
    int base = tmp[t] - pair;   // exclusive prefix

    // zero-init padded_idx, then scatter kept indices (stable order)
    if (e0 < S) g_idx[(long)b * S + e0] = 0;
    if (e1 < S) g_idx[(long)b * S + e1] = 0;
    __syncthreads();
    if (k0) g_idx[(long)b * S + base]      = e0;
    if (k1) g_idx[(long)b * S + base + k0] = e1;
    __syncthreads();

    // attention mask rewrite:
    // am[b,p] = mask[b, idx] - (idx==0 ? NEG : 0) + (p==0 ? NEG : 0)
    #pragma unroll
    for (int j = 0; j < 2; ++j) {
        int p = 2 * t + j;
        if (p < S) {
            int idx = g_idx[(long)b * S + p];
            float v = attn_mask[(long)b * S + idx];
            if (idx == 0) v -= NEG_CONST;
            if (p == 0)   v += NEG_CONST;
            am_out[(long)b * S + p] = v;
        }
    }
}

// ---------------------------------------------------------------------------
// Kernel 3: gather hidden_states rows per padded_idx.
// grid = B*S, block = 256, float4 per thread (D=1024 -> one iter)
// ---------------------------------------------------------------------------
__global__ void tp_gather_kernel(const float4* __restrict__ hs,
                                 float4* __restrict__ out, int S, int D4) {
    int pos = blockIdx.x;
    int b   = pos / S;
    int src = g_idx[pos];
    const float4* sp = hs + ((long)b * S + src) * (long)D4;
    float4* dp = out + (long)pos * D4;
    for (int t = threadIdx.x; t < D4; t += blockDim.x) dp[t] = sp[t];
}

// ---------------------------------------------------------------------------
extern "C" void kernel_launch(void* const* d_in, const int* in_sizes, int n_in,
                              void* d_out, int out_size) {
    const float* hidden  = (const float*)d_in[0];   // [B,S,D]
    const float* attn    = (const float*)d_in[1];   // [B,H,S,S]
    const float* hm      = (const float*)d_in[2];   // [H]
    const float* amask   = (const float*)d_in[3];   // [B,1,1,S]
    const float* thr     = (const float*)d_in[4];   // [1]

    int H      = in_sizes[2];
    long n_bs  = (long)in_sizes[3];                 // B*S
    long n_att = (long)in_sizes[1];                 // B*H*S*S
    int S      = (int)(n_att / n_bs / H);
    int B      = (int)(n_bs / S);
    int D      = (int)((long)in_sizes[0] / n_bs);

    float* out_hs = (float*)d_out;                  // [B,S,D]
    float* out_am = (float*)d_out + (long)B * S * D; // [B,1,1,S]

    // 0) zero score accumulator
    {
        int n = B * S;
        tp_zero_kernel<<<(n + 255) / 256, 256>>>(n);
    }

    // 1) weighted column-sum of attention_probs
    {
        const int Q_SPLITS = 16;
        int S4      = S >> 2;
        int kblocks = (S4 + 255) / 256;
        int q_per   = (S + Q_SPLITS - 1) / Q_SPLITS;
        dim3 grid(kblocks, Q_SPLITS, B * H);
        tp_colsum_kernel<<<grid, 256>>>((const float4*)attn, hm, S, H, q_per);
    }

    // 2) threshold + stable compaction + mask rewrite
    tp_prune_scan_kernel<<<B, 1024>>>(hm, H, amask, thr, out_am, S);

    // 3) gather hidden_states rows
    tp_gather_kernel<<<B * S, 256>>>((const float4*)hidden, (float4*)out_hs,
                                     S, D / 4);
}